// round 1
// baseline (speedup 1.0000x reference)
#include <cuda_runtime.h>
#include <math.h>

#define B_  512
#define Z_  64
#define H_  256
#define T_  64
#define P_  10000
#define G3_ 768
#define BT_ (B_*T_)

// ---------------- scratch (no allocations allowed) ----------------
__device__ float g_h0[B_*H_];                 // elu(z @ W_init^T + b)
__device__ float g_gx0[G3_];                  // input gates for layer 0 (same for all b,t)
__device__ float g_WT0[H_*G3_];               // W_hh0 transposed to [k][gate]
__device__ float g_WT1[H_*G3_];
__device__ float g_y0[BT_*H_];                // layer-0 output, then reused for layer-1 output
__device__ float g_yln[BT_*H_];               // LN+ELU output (A matrix of final GEMM)
__device__ float g_gx1[(size_t)BT_*G3_];      // input gates for layer 1 (100 MB)

__device__ __forceinline__ float elu1(float x) {
    return x > 0.f ? x : (__expf(x) - 1.f);
}

// ---------------- prep kernels ----------------
__global__ void k_transpose(const float* __restrict__ W, float* __restrict__ WT) {
    int idx = blockIdx.x * 256 + threadIdx.x;   // H_*G3_
    int k = idx / G3_, g = idx - k * G3_;
    WT[idx] = W[g * H_ + k];
}

__global__ void k_h0(const float* __restrict__ z, const float* __restrict__ Wi,
                     const float* __restrict__ bi) {
    int idx = blockIdx.x * 256 + threadIdx.x;   // B_*H_
    int b = idx >> 8, h = idx & 255;
    float s = bi[h];
    const float* zr = z + b * Z_;
    const float* wr = Wi + h * Z_;
#pragma unroll 16
    for (int i = 0; i < Z_; i++) s += zr[i] * wr[i];
    g_h0[idx] = elu1(s);
}

__global__ void k_gx0(const float* __restrict__ emb, const float* __restrict__ Wih,
                      const float* __restrict__ bih) {
    int g = blockIdx.x * 256 + threadIdx.x;     // G3_
    float s = bih[g];
    const float* wr = Wih + g * H_;
#pragma unroll 8
    for (int i = 0; i < H_; i++) s += emb[i] * wr[i];
    g_gx0[g] = s;
}

// ---------------- GRU scan: one block owns BB batch rows, loops all T steps ----
#define BB 4
__global__ __launch_bounds__(256) void gru_scan(
        const float* __restrict__ WT,    // [H_][G3_]  (k-major)
        const float* __restrict__ bhh,   // [G3_]
        const float* __restrict__ gx,    // layer0: [G3_]; layer1: [BT_][G3_]
        int gx_per_bt,
        float* __restrict__ y) {
    __shared__ __align__(16) float h_s [BB][H_];
    __shared__ __align__(16) float gh_s[BB][G3_];
    __shared__ __align__(16) float gx_s[BB][G3_];
    int tid = threadIdx.x;
    int b0 = blockIdx.x * BB;

#pragma unroll
    for (int r = 0; r < BB; r++) h_s[r][tid] = g_h0[(b0 + r) * H_ + tid];
    if (!gx_per_bt) {
        for (int i = tid; i < G3_; i += 256) gx_s[0][i] = gx[i];
    }
    float4 bias4 = make_float4(0.f, 0.f, 0.f, 0.f);
    if (tid < 192) bias4 = *(const float4*)(bhh + tid * 4);
    __syncthreads();

    for (int step = 0; step < T_; step++) {
        if (gx_per_bt) {
            // stage this step's input gates (4 rows x 768) coalesced (float4)
#pragma unroll
            for (int i = 0; i < 3; i++) {
                int j = tid + i * 256;              // 0..767
                int r = j / 192;
                int c = (j - r * 192) * 4;
                *(float4*)&gx_s[r][c] =
                    *(const float4*)&gx[((size_t)(b0 + r) * T_ + step) * G3_ + c];
            }
            // no sync needed: gx_s is only read after the post-mainloop sync
        }
        // gh = h @ Whh^T  : thread t (t<192) computes gates 4t..4t+3 for all BB rows
        float acc[BB][4];
#pragma unroll
        for (int r = 0; r < BB; r++) { acc[r][0]=0.f; acc[r][1]=0.f; acc[r][2]=0.f; acc[r][3]=0.f; }
        if (tid < 192) {
            const float* wp = WT + tid * 4;
#pragma unroll 4
            for (int k = 0; k < H_; k += 4) {
                float4 w0 = *(const float4*)(wp + (size_t)(k+0) * G3_);
                float4 w1 = *(const float4*)(wp + (size_t)(k+1) * G3_);
                float4 w2 = *(const float4*)(wp + (size_t)(k+2) * G3_);
                float4 w3 = *(const float4*)(wp + (size_t)(k+3) * G3_);
#pragma unroll
                for (int r = 0; r < BB; r++) {
                    float4 hv = *(const float4*)&h_s[r][k];
                    acc[r][0] += hv.x*w0.x + hv.y*w1.x + hv.z*w2.x + hv.w*w3.x;
                    acc[r][1] += hv.x*w0.y + hv.y*w1.y + hv.z*w2.y + hv.w*w3.y;
                    acc[r][2] += hv.x*w0.z + hv.y*w1.z + hv.z*w2.z + hv.w*w3.z;
                    acc[r][3] += hv.x*w0.w + hv.y*w1.w + hv.z*w2.w + hv.w*w3.w;
                }
            }
#pragma unroll
            for (int r = 0; r < BB; r++) {
                float4 gv = make_float4(acc[r][0]+bias4.x, acc[r][1]+bias4.y,
                                        acc[r][2]+bias4.z, acc[r][3]+bias4.w);
                *(float4*)&gh_s[r][tid*4] = gv;
            }
        }
        __syncthreads();
        // gate math: thread t handles hidden unit t for all BB rows
#pragma unroll
        for (int r = 0; r < BB; r++) {
            int gr = gx_per_bt ? r : 0;
            float xr = gx_s[gr][tid], xz = gx_s[gr][H_+tid], xn = gx_s[gr][2*H_+tid];
            float hr = gh_s[r ][tid], hz = gh_s[r ][H_+tid], hn = gh_s[r ][2*H_+tid];
            float rg = 1.f / (1.f + __expf(-(xr + hr)));
            float ug = 1.f / (1.f + __expf(-(xz + hz)));
            float ng = tanhf(xn + rg * hn);
            float hold = h_s[r][tid];
            float hnew = (1.f - ug) * ng + ug * hold;
            h_s[r][tid] = hnew;
            y[((size_t)(b0 + r) * T_ + step) * H_ + tid] = hnew;
        }
        __syncthreads();
    }
}

// ---------------- LayerNorm + ELU (one warp per (b,t) row) ----------------
__global__ void k_ln_elu(const float* __restrict__ y, const float* __restrict__ lng,
                         const float* __restrict__ lnb) {
    int warp = threadIdx.x >> 5, lane = threadIdx.x & 31;
    int row = blockIdx.x * 8 + warp;
    const float* p = y + (size_t)row * H_;
    float v[8], s = 0.f, sq = 0.f;
#pragma unroll
    for (int i = 0; i < 8; i++) { v[i] = p[lane + 32*i]; s += v[i]; sq += v[i]*v[i]; }
#pragma unroll
    for (int o = 16; o; o >>= 1) {
        s  += __shfl_xor_sync(0xffffffffu, s,  o);
        sq += __shfl_xor_sync(0xffffffffu, sq, o);
    }
    float mu  = s  * (1.f / H_);
    float var = sq * (1.f / H_) - mu * mu;
    float inv = rsqrtf(var + 1e-5f);
    float* o = g_yln + (size_t)row * H_;
#pragma unroll
    for (int i = 0; i < 8; i++) {
        int c = lane + 32*i;
        float t = (v[i] - mu) * inv * lng[c] + lnb[c];
        o[c] = elu1(t);
    }
}

// ---------------- SGEMM: C[M,N] = A[M,256] @ W[N,256]^T + bias ----------------
// 128x128 tile, BK=8, 256 threads, 8x8 microtile. M multiple of 128; N guarded.
__global__ __launch_bounds__(256, 2) void sgemm_nt(
        const float* __restrict__ A, const float* __restrict__ W,
        const float* __restrict__ bias, float* __restrict__ C, int N) {
    __shared__ __align__(16) float As[8][128];
    __shared__ __align__(16) float Ws[8][132];
    int tid = threadIdx.x;
    int m0 = blockIdx.y * 128;
    int n0 = blockIdx.x * 128;
    int lrow = tid >> 1;
    int lk   = (tid & 1) * 4;
    int tx = tid & 15, ty = tid >> 4;

    float acc[8][8];
#pragma unroll
    for (int i = 0; i < 8; i++)
#pragma unroll
        for (int j = 0; j < 8; j++) acc[i][j] = 0.f;

    const float* Ap = A + (size_t)(m0 + lrow) * 256 + lk;
    int wr = n0 + lrow;
    const float* Wp = W + (size_t)wr * 256 + lk;
    bool wok = wr < N;

    for (int k0 = 0; k0 < 256; k0 += 8) {
        float4 av = *(const float4*)(Ap + k0);
        float4 wv = wok ? *(const float4*)(Wp + k0) : make_float4(0.f,0.f,0.f,0.f);
        __syncthreads();
        As[lk+0][lrow] = av.x; As[lk+1][lrow] = av.y; As[lk+2][lrow] = av.z; As[lk+3][lrow] = av.w;
        Ws[lk+0][lrow] = wv.x; Ws[lk+1][lrow] = wv.y; Ws[lk+2][lrow] = wv.z; Ws[lk+3][lrow] = wv.w;
        __syncthreads();
#pragma unroll
        for (int kk = 0; kk < 8; kk++) {
            float a[8], w[8];
            *(float4*)(a)   = *(const float4*)&As[kk][ty*8];
            *(float4*)(a+4) = *(const float4*)&As[kk][ty*8+4];
            *(float4*)(w)   = *(const float4*)&Ws[kk][tx*8];
            *(float4*)(w+4) = *(const float4*)&Ws[kk][tx*8+4];
#pragma unroll
            for (int i = 0; i < 8; i++)
#pragma unroll
                for (int j = 0; j < 8; j++) acc[i][j] += a[i] * w[j];
        }
    }
    float br[8];
#pragma unroll
    for (int j = 0; j < 8; j++) {
        int n = n0 + tx*8 + j;
        br[j] = (n < N) ? bias[n] : 0.f;
    }
#pragma unroll
    for (int i = 0; i < 8; i++) {
        int m = m0 + ty*8 + i;
        float* crow = C + (size_t)m * N;
#pragma unroll
        for (int j = 0; j < 8; j++) {
            int n = n0 + tx*8 + j;
            if (n < N) crow[n] = acc[i][j] + br[j];
        }
    }
}

// ---------------- launch ----------------
extern "C" void kernel_launch(void* const* d_in, const int* in_sizes, int n_in,
                              void* d_out, int out_size) {
    const float* z      = (const float*)d_in[0];
    const float* W_init = (const float*)d_in[1];
    const float* b_init = (const float*)d_in[2];
    const float* emb    = (const float*)d_in[3];
    const float* W_ih0  = (const float*)d_in[4];
    const float* W_hh0  = (const float*)d_in[5];
    // b_ih0 = d_in[6] folded into gx0
    const float* b_ih0  = (const float*)d_in[6];
    const float* b_hh0  = (const float*)d_in[7];
    const float* W_ih1  = (const float*)d_in[8];
    const float* W_hh1  = (const float*)d_in[9];
    const float* b_ih1  = (const float*)d_in[10];
    const float* b_hh1  = (const float*)d_in[11];
    const float* ln_g   = (const float*)d_in[12];
    const float* ln_b   = (const float*)d_in[13];
    const float* W_out  = (const float*)d_in[14];
    const float* b_out  = (const float*)d_in[15];

    float *p_WT0, *p_WT1, *p_y0, *p_gx0, *p_gx1, *p_yln;
    cudaGetSymbolAddress((void**)&p_WT0, g_WT0);
    cudaGetSymbolAddress((void**)&p_WT1, g_WT1);
    cudaGetSymbolAddress((void**)&p_y0,  g_y0);
    cudaGetSymbolAddress((void**)&p_gx0, g_gx0);
    cudaGetSymbolAddress((void**)&p_gx1, g_gx1);
    cudaGetSymbolAddress((void**)&p_yln, g_yln);

    // prep
    k_transpose<<<H_*G3_/256, 256>>>(W_hh0, p_WT0);
    k_transpose<<<H_*G3_/256, 256>>>(W_hh1, p_WT1);
    k_h0<<<B_*H_/256, 256>>>(z, W_init, b_init);
    k_gx0<<<G3_/256, 256>>>(emb, W_ih0, b_ih0);

    // layer 0 scan (input gates constant across b,t)
    gru_scan<<<B_/BB, 256>>>(p_WT0, b_hh0, p_gx0, 0, p_y0);

    // layer-1 input gates: gx1 = y0 @ W_ih1^T + b_ih1
    sgemm_nt<<<dim3(G3_/128, BT_/128), 256>>>(p_y0, W_ih1, b_ih1, p_gx1, G3_);

    // layer 1 scan (output overwrites g_y0; scan reads only g_gx1/g_h0)
    gru_scan<<<B_/BB, 256>>>(p_WT1, b_hh1, p_gx1, 1, p_y0);

    // LayerNorm + ELU
    k_ln_elu<<<BT_/8, 256>>>(p_y0, ln_g, ln_b);

    // logits = yln @ W_out^T + b_out
    sgemm_nt<<<dim3((P_ + 127)/128, BT_/128), 256>>>(p_yln, W_out, b_out,
                                                     (float*)d_out, P_);
}

// round 3
// speedup vs baseline: 1.6717x; 1.6717x over previous
#include <cuda_runtime.h>
#include <cuda_bf16.h>
#include <cstdint>
#include <math.h>

#define B_  512
#define Z_  64
#define H_  256
#define T_  64
#define P_  10000
#define G3_ 768
#define BT_ (B_*T_)
#define PPAD 10112   // 79*128
#define KS_ 768      // split-K: [Ah, Ah, Al] x [Wh, Wl, Wh]

// ---------------- scratch (no allocations allowed) ----------------
__device__ float g_h0[B_*H_];
__device__ float g_gx0[G3_];
__device__ float g_WT0[H_*G3_];
__device__ float g_WT1[H_*G3_];
__device__ float g_y0[BT_*H_];
__device__ float g_gx1[(size_t)BT_*G3_];
__device__ __align__(256) __nv_bfloat16 g_A2y0[(size_t)BT_*KS_];
__device__ __align__(256) __nv_bfloat16 g_A2out[(size_t)BT_*KS_];
__device__ __align__(256) __nv_bfloat16 g_Wb2[(size_t)PPAD*KS_];
__device__ __align__(256) __nv_bfloat16 g_Wih1b2[(size_t)G3_*KS_];

__device__ __forceinline__ float elu1(float x) {
    return x > 0.f ? x : (__expf(x) - 1.f);
}

__device__ __forceinline__ uint32_t smem_u32(const void* p) {
    uint32_t a;
    asm("{ .reg .u64 t; cvta.to.shared.u64 t, %1; cvt.u32.u64 %0, t; }" : "=r"(a) : "l"(p));
    return a;
}
__device__ __forceinline__ void cp16(uint32_t s, const void* g) {
    asm volatile("cp.async.cg.shared.global [%0], [%1], 16;" :: "r"(s), "l"(g));
}
__device__ __forceinline__ void ldsm4(uint32_t& a0, uint32_t& a1, uint32_t& a2, uint32_t& a3,
                                      uint32_t addr) {
    asm volatile("ldmatrix.sync.aligned.m8n8.x4.shared.b16 {%0,%1,%2,%3}, [%4];"
        : "=r"(a0), "=r"(a1), "=r"(a2), "=r"(a3) : "r"(addr));
}
__device__ __forceinline__ void mma16816(float* d, uint32_t a0, uint32_t a1, uint32_t a2,
                                         uint32_t a3, uint32_t b0, uint32_t b1) {
    asm volatile("mma.sync.aligned.m16n8k16.row.col.f32.bf16.bf16.f32 "
        "{%0,%1,%2,%3}, {%4,%5,%6,%7}, {%8,%9}, {%0,%1,%2,%3};"
        : "+f"(d[0]), "+f"(d[1]), "+f"(d[2]), "+f"(d[3])
        : "r"(a0), "r"(a1), "r"(a2), "r"(a3), "r"(b0), "r"(b1));
}

// ================= bf16 split-K tensor GEMM: C[M,ldc] = A2[M,768] @ B2[N,768]^T + bias
// 128x128 tile, 8 warps (4 m x 2 n), warp tile 32x64, K chunks of 64, double buffer.
#define CH_B 16384   // bytes per (128x64 bf16) buffer
__global__ __launch_bounds__(256, 2) void gemm_mma(
        const __nv_bfloat16* __restrict__ A2, const __nv_bfloat16* __restrict__ B2,
        const float* __restrict__ bias, float* __restrict__ C, int N, int ldc) {
    extern __shared__ char sm[];
    const uint32_t sbase = smem_u32(sm);
    const int tid = threadIdx.x, lane = tid & 31, wid = tid >> 5;
    const int m0t = blockIdx.y << 7, n0t = blockIdx.x << 7;

    // ---- cp.async mapping: thread covers 4 consecutive 16B units of one row
    const int lrow = tid >> 1;
    const int lkb  = (tid & 1) * 4;
    uint32_t lsoff[4];
#pragma unroll
    for (int j = 0; j < 4; ++j)
        lsoff[j] = lrow * 128 + ((((lkb + j) << 4)) ^ ((lrow & 7) << 4));
    const char* gAr = (const char*)A2 + (size_t)(m0t + lrow) * (KS_ * 2) + lkb * 16;
    const char* gBr = (const char*)B2 + (size_t)(n0t + lrow) * (KS_ * 2) + lkb * 16;

    // ---- ldmatrix per-thread addressing
    const int g = lane >> 3, r = lane & 7;
    const uint32_t rx = r << 4;
    const uint32_t aKbx = (g >> 1) << 4;                 // 0 or 16 bytes
    const uint32_t bKbx = (g & 1) << 4;
    uint32_t aRowOff[2], bRowOff[4];
#pragma unroll
    for (int fm = 0; fm < 2; ++fm)
        aRowOff[fm] = (uint32_t)(((wid & 3) * 32 + ((g & 1) << 3) + r + fm * 16) * 128);
#pragma unroll
    for (int p = 0; p < 4; ++p)
        bRowOff[p] = (uint32_t)(((wid >> 2) * 64 + ((g >> 1) << 3) + r + p * 16) * 128);

    float acc[2][8][4];
#pragma unroll
    for (int i = 0; i < 2; ++i)
#pragma unroll
        for (int j = 0; j < 8; ++j)
#pragma unroll
            for (int k = 0; k < 4; ++k) acc[i][j][k] = 0.f;

    // prologue: chunk 0 -> buf 0
#pragma unroll
    for (int j = 0; j < 4; ++j) {
        cp16(sbase + lsoff[j], gAr + j * 16);
        cp16(sbase + 32768 + lsoff[j], gBr + j * 16);
    }
    asm volatile("cp.async.commit_group;");

    for (int c = 0; c < 12; ++c) {
        const int buf = c & 1;
        if (c < 11) {
            const int nb = buf ^ 1;
            const char* pa = gAr + (c + 1) * 128;
            const char* pb = gBr + (c + 1) * 128;
#pragma unroll
            for (int j = 0; j < 4; ++j) {
                cp16(sbase + nb * CH_B + lsoff[j], pa + j * 16);
                cp16(sbase + 32768 + nb * CH_B + lsoff[j], pb + j * 16);
            }
            asm volatile("cp.async.commit_group;");
            asm volatile("cp.async.wait_group 1;");
        } else {
            asm volatile("cp.async.wait_group 0;");
        }
        __syncthreads();

        const uint32_t aB = sbase + buf * CH_B;
        const uint32_t bB = sbase + 32768 + buf * CH_B;
#pragma unroll
        for (int kk = 0; kk < 4; ++kk) {
            const uint32_t akoff = ((uint32_t)(kk * 32) + aKbx) ^ rx;
            const uint32_t bkoff = ((uint32_t)(kk * 32) + bKbx) ^ rx;
            uint32_t a[2][4], bb[4][4];
#pragma unroll
            for (int fm = 0; fm < 2; ++fm)
                ldsm4(a[fm][0], a[fm][1], a[fm][2], a[fm][3], aB + aRowOff[fm] + akoff);
#pragma unroll
            for (int p = 0; p < 4; ++p)
                ldsm4(bb[p][0], bb[p][1], bb[p][2], bb[p][3], bB + bRowOff[p] + bkoff);
#pragma unroll
            for (int fm = 0; fm < 2; ++fm)
#pragma unroll
                for (int p = 0; p < 4; ++p) {
                    mma16816(acc[fm][2 * p],     a[fm][0], a[fm][1], a[fm][2], a[fm][3],
                             bb[p][0], bb[p][1]);
                    mma16816(acc[fm][2 * p + 1], a[fm][0], a[fm][1], a[fm][2], a[fm][3],
                             bb[p][2], bb[p][3]);
                }
        }
        __syncthreads();
    }

    // epilogue
#pragma unroll
    for (int fm = 0; fm < 2; ++fm) {
        const int mrow = m0t + (wid & 3) * 32 + fm * 16 + (lane >> 2);
        float* c0 = C + (size_t)mrow * ldc;
        float* c1 = C + (size_t)(mrow + 8) * ldc;
#pragma unroll
        for (int bn = 0; bn < 8; ++bn) {
            const int n = n0t + (wid >> 2) * 64 + bn * 8 + (lane & 3) * 2;
            if (n < N) {
                const float bv = bias[n];
                c0[n] = acc[fm][bn][0] + bv;
                c1[n] = acc[fm][bn][2] + bv;
            }
            if (n + 1 < N) {
                const float bv = bias[n + 1];
                c0[n + 1] = acc[fm][bn][1] + bv;
                c1[n + 1] = acc[fm][bn][3] + bv;
            }
        }
    }
}

// ---------------- prep kernels ----------------
__global__ void k_transpose(const float* __restrict__ W, float* __restrict__ WT) {
    int idx = blockIdx.x * 256 + threadIdx.x;
    int k = idx / G3_, g = idx - k * G3_;
    WT[idx] = W[g * H_ + k];
}

__global__ void k_h0(const float* __restrict__ z, const float* __restrict__ Wi,
                     const float* __restrict__ bi) {
    int idx = blockIdx.x * 256 + threadIdx.x;
    int b = idx >> 8, h = idx & 255;
    float s = bi[h];
    const float* zr = z + b * Z_;
    const float* wr = Wi + h * Z_;
#pragma unroll 16
    for (int i = 0; i < Z_; i++) s += zr[i] * wr[i];
    g_h0[idx] = elu1(s);
}

__global__ void k_gx0(const float* __restrict__ emb, const float* __restrict__ Wih,
                      const float* __restrict__ bih) {
    int gg = blockIdx.x * 256 + threadIdx.x;
    float s = bih[gg];
    const float* wr = Wih + gg * H_;
#pragma unroll 8
    for (int i = 0; i < H_; i++) s += emb[i] * wr[i];
    g_gx0[gg] = s;
}

// weights: [Wh, Wl, Wh]
__global__ void k_wsplit(const float* __restrict__ W, __nv_bfloat16* __restrict__ O, int N) {
    int idx = blockIdx.x * 256 + threadIdx.x;
    int row = idx >> 8, col = idx & 255;
    float x = (row < N) ? W[row * 256 + col] : 0.f;
    __nv_bfloat16 hi = __float2bfloat16(x);
    float lo = x - __bfloat162float(hi);
    size_t base = (size_t)row * KS_;
    O[base + col]       = hi;
    O[base + 256 + col] = __float2bfloat16(lo);
    O[base + 512 + col] = hi;
}

// activations: [Ah, Ah, Al]
__device__ __forceinline__ void store_act_split(__nv_bfloat16* dst, size_t row, int col, float v) {
    __nv_bfloat16 hi = __float2bfloat16(v);
    float lo = v - __bfloat162float(hi);
    size_t base = row * KS_;
    dst[base + col]       = hi;
    dst[base + 256 + col] = hi;
    dst[base + 512 + col] = __float2bfloat16(lo);
}

// ---------------- GRU scan ----------------
#define BB 4
__global__ __launch_bounds__(256) void gru_scan(
        const float* __restrict__ WT, const float* __restrict__ bhh,
        const float* __restrict__ gx, int gx_per_bt,
        float* __restrict__ y, int out_mode) {   // 0: split bf16 -> g_A2y0 ; 1: fp32 -> y
    __shared__ __align__(16) float h_s [BB][H_];
    __shared__ __align__(16) float gh_s[BB][G3_];
    __shared__ __align__(16) float gx_s[BB][G3_];
    int tid = threadIdx.x;
    int b0 = blockIdx.x * BB;

#pragma unroll
    for (int rr = 0; rr < BB; rr++) h_s[rr][tid] = g_h0[(b0 + rr) * H_ + tid];
    if (!gx_per_bt) {
        for (int i = tid; i < G3_; i += 256) gx_s[0][i] = gx[i];
    }
    float4 bias4 = make_float4(0.f, 0.f, 0.f, 0.f);
    if (tid < 192) bias4 = *(const float4*)(bhh + tid * 4);
    __syncthreads();

    for (int step = 0; step < T_; step++) {
        if (gx_per_bt) {
#pragma unroll
            for (int i = 0; i < 3; i++) {
                int j = tid + i * 256;
                int rr = j / 192;
                int cc = (j - rr * 192) * 4;
                *(float4*)&gx_s[rr][cc] =
                    *(const float4*)&gx[((size_t)(b0 + rr) * T_ + step) * G3_ + cc];
            }
        }
        float acc[BB][4];
#pragma unroll
        for (int rr = 0; rr < BB; rr++) { acc[rr][0]=0.f; acc[rr][1]=0.f; acc[rr][2]=0.f; acc[rr][3]=0.f; }
        if (tid < 192) {
            const float* wp = WT + tid * 4;
#pragma unroll 4
            for (int k = 0; k < H_; k += 4) {
                float4 w0 = *(const float4*)(wp + (size_t)(k+0) * G3_);
                float4 w1 = *(const float4*)(wp + (size_t)(k+1) * G3_);
                float4 w2 = *(const float4*)(wp + (size_t)(k+2) * G3_);
                float4 w3 = *(const float4*)(wp + (size_t)(k+3) * G3_);
#pragma unroll
                for (int rr = 0; rr < BB; rr++) {
                    float4 hv = *(const float4*)&h_s[rr][k];
                    acc[rr][0] += hv.x*w0.x + hv.y*w1.x + hv.z*w2.x + hv.w*w3.x;
                    acc[rr][1] += hv.x*w0.y + hv.y*w1.y + hv.z*w2.y + hv.w*w3.y;
                    acc[rr][2] += hv.x*w0.z + hv.y*w1.z + hv.z*w2.z + hv.w*w3.z;
                    acc[rr][3] += hv.x*w0.w + hv.y*w1.w + hv.z*w2.w + hv.w*w3.w;
                }
            }
#pragma unroll
            for (int rr = 0; rr < BB; rr++) {
                float4 gv = make_float4(acc[rr][0]+bias4.x, acc[rr][1]+bias4.y,
                                        acc[rr][2]+bias4.z, acc[rr][3]+bias4.w);
                *(float4*)&gh_s[rr][tid*4] = gv;
            }
        }
        __syncthreads();
#pragma unroll
        for (int rr = 0; rr < BB; rr++) {
            int gr = gx_per_bt ? rr : 0;
            float xr = gx_s[gr][tid], xz = gx_s[gr][H_+tid], xn = gx_s[gr][2*H_+tid];
            float hr = gh_s[rr][tid], hz = gh_s[rr][H_+tid], hn = gh_s[rr][2*H_+tid];
            float rg = 1.f / (1.f + __expf(-(xr + hr)));
            float ug = 1.f / (1.f + __expf(-(xz + hz)));
            float ng = tanhf(xn + rg * hn);
            float hold = h_s[rr][tid];
            float hnew = (1.f - ug) * ng + ug * hold;
            h_s[rr][tid] = hnew;
            size_t row = (size_t)(b0 + rr) * T_ + step;
            if (out_mode == 0) store_act_split(g_A2y0, row, tid, hnew);
            else               y[row * H_ + tid] = hnew;
        }
        __syncthreads();
    }
}

// ---------------- LayerNorm + ELU -> split bf16 ----------------
__global__ void k_ln_elu(const float* __restrict__ y, const float* __restrict__ lng,
                         const float* __restrict__ lnb) {
    int warp = threadIdx.x >> 5, lane = threadIdx.x & 31;
    int row = blockIdx.x * 8 + warp;
    const float* p = y + (size_t)row * H_;
    float v[8], s = 0.f, sq = 0.f;
#pragma unroll
    for (int i = 0; i < 8; i++) { v[i] = p[lane + 32*i]; s += v[i]; sq += v[i]*v[i]; }
#pragma unroll
    for (int o = 16; o; o >>= 1) {
        s  += __shfl_xor_sync(0xffffffffu, s,  o);
        sq += __shfl_xor_sync(0xffffffffu, sq, o);
    }
    float mu  = s  * (1.f / H_);
    float var = sq * (1.f / H_) - mu * mu;
    float inv = rsqrtf(var + 1e-5f);
#pragma unroll
    for (int i = 0; i < 8; i++) {
        int c = lane + 32*i;
        float t = elu1((v[i] - mu) * inv * lng[c] + lnb[c]);
        store_act_split(g_A2out, (size_t)row, c, t);
    }
}

// ---------------- launch ----------------
extern "C" void kernel_launch(void* const* d_in, const int* in_sizes, int n_in,
                              void* d_out, int out_size) {
    const float* z      = (const float*)d_in[0];
    const float* W_init = (const float*)d_in[1];
    const float* b_init = (const float*)d_in[2];
    const float* emb    = (const float*)d_in[3];
    const float* W_ih0  = (const float*)d_in[4];
    const float* W_hh0  = (const float*)d_in[5];
    const float* b_ih0  = (const float*)d_in[6];
    const float* b_hh0  = (const float*)d_in[7];
    const float* W_ih1  = (const float*)d_in[8];
    const float* W_hh1  = (const float*)d_in[9];
    const float* b_ih1  = (const float*)d_in[10];
    const float* b_hh1  = (const float*)d_in[11];
    const float* ln_g   = (const float*)d_in[12];
    const float* ln_b   = (const float*)d_in[13];
    const float* W_out  = (const float*)d_in[14];
    const float* b_out  = (const float*)d_in[15];

    float *p_WT0, *p_WT1, *p_y0, *p_gx0, *p_gx1;
    __nv_bfloat16 *p_A2y0, *p_A2out, *p_Wb2, *p_Wih1b2;
    cudaGetSymbolAddress((void**)&p_WT0, g_WT0);
    cudaGetSymbolAddress((void**)&p_WT1, g_WT1);
    cudaGetSymbolAddress((void**)&p_y0,  g_y0);
    cudaGetSymbolAddress((void**)&p_gx0, g_gx0);
    cudaGetSymbolAddress((void**)&p_gx1, g_gx1);
    cudaGetSymbolAddress((void**)&p_A2y0, g_A2y0);
    cudaGetSymbolAddress((void**)&p_A2out, g_A2out);
    cudaGetSymbolAddress((void**)&p_Wb2, g_Wb2);
    cudaGetSymbolAddress((void**)&p_Wih1b2, g_Wih1b2);

    cudaFuncSetAttribute(gemm_mma, cudaFuncAttributeMaxDynamicSharedMemorySize, 65536);

    // weight prep (independent)
    k_transpose<<<H_*G3_/256, 256>>>(W_hh0, p_WT0);
    k_transpose<<<H_*G3_/256, 256>>>(W_hh1, p_WT1);
    k_wsplit<<<G3_, 256>>>(W_ih1, p_Wih1b2, G3_);
    k_wsplit<<<PPAD, 256>>>(W_out, p_Wb2, P_);
    k_h0<<<B_*H_/256, 256>>>(z, W_init, b_init);
    k_gx0<<<G3_/256, 256>>>(emb, W_ih0, b_ih0);

    // layer 0 scan -> split bf16 A
    gru_scan<<<B_/BB, 256>>>(p_WT0, b_hh0, p_gx0, 0, nullptr, 0);

    // gx1 = y0 @ W_ih1^T + b_ih1  (tensor cores)
    gemm_mma<<<dim3(G3_/128, BT_/128), 256, 65536>>>(p_A2y0, p_Wih1b2, b_ih1, p_gx1, G3_, G3_);

    // layer 1 scan -> fp32 y
    gru_scan<<<B_/BB, 256>>>(p_WT1, b_hh1, p_gx1, 1, p_y0, 1);

    // LayerNorm + ELU -> split bf16 A
    k_ln_elu<<<BT_/8, 256>>>(p_y0, ln_g, ln_b);

    // logits = yln @ W_out^T + b_out
    gemm_mma<<<dim3(PPAD/128, BT_/128), 256, 65536>>>(p_A2out, p_Wb2, b_out, (float*)d_out, P_, P_);
}

// round 4
// speedup vs baseline: 1.6826x; 1.0065x over previous
#include <cuda_runtime.h>
#include <cuda_bf16.h>
#include <cstdint>
#include <math.h>

#define B_  512
#define Z_  64
#define H_  256
#define T_  64
#define P_  10000
#define G3_ 768
#define BT_ (B_*T_)
#define PPAD 10112   // 79*128
#define KS_ 768      // split-K: [Ah, Ah, Al] x [Wh, Wl, Wh]

// ---------------- scratch (no allocations allowed) ----------------
__device__ float g_h0[B_*H_];
__device__ float g_gx0[G3_];
__device__ float g_WT0[H_*G3_];
__device__ float g_WT1[H_*G3_];
__device__ float g_y0[BT_*H_];
__device__ float g_gx1[(size_t)BT_*G3_];
__device__ __align__(256) __nv_bfloat16 g_A2y0[(size_t)BT_*KS_];
__device__ __align__(256) __nv_bfloat16 g_A2out[(size_t)BT_*KS_];
__device__ __align__(256) __nv_bfloat16 g_Wb2[(size_t)PPAD*KS_];
__device__ __align__(256) __nv_bfloat16 g_Wih1b2[(size_t)G3_*KS_];

__device__ __forceinline__ float elu1(float x) {
    return x > 0.f ? x : (__expf(x) - 1.f);
}

__device__ __forceinline__ uint32_t smem_u32(const void* p) {
    uint32_t a;
    asm("{ .reg .u64 t; cvta.to.shared.u64 t, %1; cvt.u32.u64 %0, t; }" : "=r"(a) : "l"(p));
    return a;
}
__device__ __forceinline__ void cp16(uint32_t s, const void* g) {
    asm volatile("cp.async.cg.shared.global [%0], [%1], 16;" :: "r"(s), "l"(g));
}
__device__ __forceinline__ void ldsm4(uint32_t& a0, uint32_t& a1, uint32_t& a2, uint32_t& a3,
                                      uint32_t addr) {
    asm volatile("ldmatrix.sync.aligned.m8n8.x4.shared.b16 {%0,%1,%2,%3}, [%4];"
        : "=r"(a0), "=r"(a1), "=r"(a2), "=r"(a3) : "r"(addr));
}
__device__ __forceinline__ void mma16816(float* d, uint32_t a0, uint32_t a1, uint32_t a2,
                                         uint32_t a3, uint32_t b0, uint32_t b1) {
    asm volatile("mma.sync.aligned.m16n8k16.row.col.f32.bf16.bf16.f32 "
        "{%0,%1,%2,%3}, {%4,%5,%6,%7}, {%8,%9}, {%0,%1,%2,%3};"
        : "+f"(d[0]), "+f"(d[1]), "+f"(d[2]), "+f"(d[3])
        : "r"(a0), "r"(a1), "r"(a2), "r"(a3), "r"(b0), "r"(b1));
}

// ================= bf16 split-K tensor GEMM: C[M,ldc] = A2[M,768] @ B2[N,768]^T + bias
// 128x128 tile, 8 warps (4 m x 2 n), warp tile 32x64, K chunks of 64, double buffer.
#define CH_B 16384   // bytes per (128x64 bf16) buffer
__global__ __launch_bounds__(256, 2) void gemm_mma(
        const __nv_bfloat16* __restrict__ A2, const __nv_bfloat16* __restrict__ B2,
        const float* __restrict__ bias, float* __restrict__ C, int N, int ldc) {
    extern __shared__ char sm[];
    const uint32_t sbase = smem_u32(sm);
    const int tid = threadIdx.x, lane = tid & 31, wid = tid >> 5;
    const int m0t = blockIdx.y << 7, n0t = blockIdx.x << 7;

    // ---- cp.async mapping: thread covers 4 consecutive 16B units of one row
    const int lrow = tid >> 1;
    const int lkb  = (tid & 1) * 4;
    uint32_t lsoff[4];
#pragma unroll
    for (int j = 0; j < 4; ++j)
        lsoff[j] = lrow * 128 + ((((lkb + j) << 4)) ^ ((lrow & 7) << 4));
    const char* gAr = (const char*)A2 + (size_t)(m0t + lrow) * (KS_ * 2) + lkb * 16;
    const char* gBr = (const char*)B2 + (size_t)(n0t + lrow) * (KS_ * 2) + lkb * 16;

    // ---- ldmatrix per-thread addressing
    const int g = lane >> 3, r = lane & 7;
    const uint32_t rx = r << 4;
    const uint32_t aKbx = (g >> 1) << 4;                 // 0 or 16 bytes
    const uint32_t bKbx = (g & 1) << 4;
    uint32_t aRowOff[2], bRowOff[4];
#pragma unroll
    for (int fm = 0; fm < 2; ++fm)
        aRowOff[fm] = (uint32_t)(((wid & 3) * 32 + ((g & 1) << 3) + r + fm * 16) * 128);
#pragma unroll
    for (int p = 0; p < 4; ++p)
        bRowOff[p] = (uint32_t)(((wid >> 2) * 64 + ((g >> 1) << 3) + r + p * 16) * 128);

    float acc[2][8][4];
#pragma unroll
    for (int i = 0; i < 2; ++i)
#pragma unroll
        for (int j = 0; j < 8; ++j)
#pragma unroll
            for (int k = 0; k < 4; ++k) acc[i][j][k] = 0.f;

    // prologue: chunk 0 -> buf 0
#pragma unroll
    for (int j = 0; j < 4; ++j) {
        cp16(sbase + lsoff[j], gAr + j * 16);
        cp16(sbase + 32768 + lsoff[j], gBr + j * 16);
    }
    asm volatile("cp.async.commit_group;");

    for (int c = 0; c < 12; ++c) {
        const int buf = c & 1;
        if (c < 11) {
            const int nb = buf ^ 1;
            const char* pa = gAr + (c + 1) * 128;
            const char* pb = gBr + (c + 1) * 128;
#pragma unroll
            for (int j = 0; j < 4; ++j) {
                cp16(sbase + nb * CH_B + lsoff[j], pa + j * 16);
                cp16(sbase + 32768 + nb * CH_B + lsoff[j], pb + j * 16);
            }
            asm volatile("cp.async.commit_group;");
            asm volatile("cp.async.wait_group 1;");
        } else {
            asm volatile("cp.async.wait_group 0;");
        }
        __syncthreads();

        const uint32_t aB = sbase + buf * CH_B;
        const uint32_t bB = sbase + 32768 + buf * CH_B;
#pragma unroll
        for (int kk = 0; kk < 4; ++kk) {
            const uint32_t akoff = ((uint32_t)(kk * 32) + aKbx) ^ rx;
            const uint32_t bkoff = ((uint32_t)(kk * 32) + bKbx) ^ rx;
            uint32_t a[2][4], bb[4][4];
#pragma unroll
            for (int fm = 0; fm < 2; ++fm)
                ldsm4(a[fm][0], a[fm][1], a[fm][2], a[fm][3], aB + aRowOff[fm] + akoff);
#pragma unroll
            for (int p = 0; p < 4; ++p)
                ldsm4(bb[p][0], bb[p][1], bb[p][2], bb[p][3], bB + bRowOff[p] + bkoff);
#pragma unroll
            for (int fm = 0; fm < 2; ++fm)
#pragma unroll
                for (int p = 0; p < 4; ++p) {
                    mma16816(acc[fm][2 * p],     a[fm][0], a[fm][1], a[fm][2], a[fm][3],
                             bb[p][0], bb[p][1]);
                    mma16816(acc[fm][2 * p + 1], a[fm][0], a[fm][1], a[fm][2], a[fm][3],
                             bb[p][2], bb[p][3]);
                }
        }
        __syncthreads();
    }

    // epilogue
#pragma unroll
    for (int fm = 0; fm < 2; ++fm) {
        const int mrow = m0t + (wid & 3) * 32 + fm * 16 + (lane >> 2);
        float* c0 = C + (size_t)mrow * ldc;
        float* c1 = C + (size_t)(mrow + 8) * ldc;
#pragma unroll
        for (int bn = 0; bn < 8; ++bn) {
            const int n = n0t + (wid >> 2) * 64 + bn * 8 + (lane & 3) * 2;
            if (n < N) {
                const float bv = bias[n];
                c0[n] = acc[fm][bn][0] + bv;
                c1[n] = acc[fm][bn][2] + bv;
            }
            if (n + 1 < N) {
                const float bv = bias[n + 1];
                c0[n + 1] = acc[fm][bn][1] + bv;
                c1[n + 1] = acc[fm][bn][3] + bv;
            }
        }
    }
}

// ---------------- prep kernels ----------------
__global__ void k_transpose(const float* __restrict__ W, float* __restrict__ WT) {
    int idx = blockIdx.x * 256 + threadIdx.x;
    int k = idx / G3_, g = idx - k * G3_;
    WT[idx] = W[g * H_ + k];
}

__global__ void k_h0(const float* __restrict__ z, const float* __restrict__ Wi,
                     const float* __restrict__ bi) {
    int idx = blockIdx.x * 256 + threadIdx.x;
    int b = idx >> 8, h = idx & 255;
    float s = bi[h];
    const float* zr = z + b * Z_;
    const float* wr = Wi + h * Z_;
#pragma unroll 16
    for (int i = 0; i < Z_; i++) s += zr[i] * wr[i];
    g_h0[idx] = elu1(s);
}

__global__ void k_gx0(const float* __restrict__ emb, const float* __restrict__ Wih,
                      const float* __restrict__ bih) {
    int gg = blockIdx.x * 256 + threadIdx.x;
    float s = bih[gg];
    const float* wr = Wih + gg * H_;
#pragma unroll 8
    for (int i = 0; i < H_; i++) s += emb[i] * wr[i];
    g_gx0[gg] = s;
}

// weights: [Wh, Wl, Wh]
__global__ void k_wsplit(const float* __restrict__ W, __nv_bfloat16* __restrict__ O, int N) {
    int idx = blockIdx.x * 256 + threadIdx.x;
    int row = idx >> 8, col = idx & 255;
    float x = (row < N) ? W[row * 256 + col] : 0.f;
    __nv_bfloat16 hi = __float2bfloat16(x);
    float lo = x - __bfloat162float(hi);
    size_t base = (size_t)row * KS_;
    O[base + col]       = hi;
    O[base + 256 + col] = __float2bfloat16(lo);
    O[base + 512 + col] = hi;
}

// activations: [Ah, Ah, Al]
__device__ __forceinline__ void store_act_split(__nv_bfloat16* dst, size_t row, int col, float v) {
    __nv_bfloat16 hi = __float2bfloat16(v);
    float lo = v - __bfloat162float(hi);
    size_t base = row * KS_;
    dst[base + col]       = hi;
    dst[base + 256 + col] = hi;
    dst[base + 512 + col] = __float2bfloat16(lo);
}

// ---------------- GRU scan ----------------
#define BB 4
__global__ __launch_bounds__(256) void gru_scan(
        const float* __restrict__ WT, const float* __restrict__ bhh,
        const float* __restrict__ gx, int gx_per_bt,
        float* __restrict__ y, int out_mode) {   // 0: split bf16 -> g_A2y0 ; 1: fp32 -> y
    __shared__ __align__(16) float h_s [BB][H_];
    __shared__ __align__(16) float gh_s[BB][G3_];
    __shared__ __align__(16) float gx_s[BB][G3_];
    int tid = threadIdx.x;
    int b0 = blockIdx.x * BB;

#pragma unroll
    for (int rr = 0; rr < BB; rr++) h_s[rr][tid] = g_h0[(b0 + rr) * H_ + tid];
    if (!gx_per_bt) {
        for (int i = tid; i < G3_; i += 256) gx_s[0][i] = gx[i];
    }
    float4 bias4 = make_float4(0.f, 0.f, 0.f, 0.f);
    if (tid < 192) bias4 = *(const float4*)(bhh + tid * 4);
    __syncthreads();

    for (int step = 0; step < T_; step++) {
        if (gx_per_bt) {
#pragma unroll
            for (int i = 0; i < 3; i++) {
                int j = tid + i * 256;
                int rr = j / 192;
                int cc = (j - rr * 192) * 4;
                *(float4*)&gx_s[rr][cc] =
                    *(const float4*)&gx[((size_t)(b0 + rr) * T_ + step) * G3_ + cc];
            }
        }
        float acc[BB][4];
#pragma unroll
        for (int rr = 0; rr < BB; rr++) { acc[rr][0]=0.f; acc[rr][1]=0.f; acc[rr][2]=0.f; acc[rr][3]=0.f; }
        if (tid < 192) {
            const float* wp = WT + tid * 4;
#pragma unroll 4
            for (int k = 0; k < H_; k += 4) {
                float4 w0 = *(const float4*)(wp + (size_t)(k+0) * G3_);
                float4 w1 = *(const float4*)(wp + (size_t)(k+1) * G3_);
                float4 w2 = *(const float4*)(wp + (size_t)(k+2) * G3_);
                float4 w3 = *(const float4*)(wp + (size_t)(k+3) * G3_);
#pragma unroll
                for (int rr = 0; rr < BB; rr++) {
                    float4 hv = *(const float4*)&h_s[rr][k];
                    acc[rr][0] += hv.x*w0.x + hv.y*w1.x + hv.z*w2.x + hv.w*w3.x;
                    acc[rr][1] += hv.x*w0.y + hv.y*w1.y + hv.z*w2.y + hv.w*w3.y;
                    acc[rr][2] += hv.x*w0.z + hv.y*w1.z + hv.z*w2.z + hv.w*w3.z;
                    acc[rr][3] += hv.x*w0.w + hv.y*w1.w + hv.z*w2.w + hv.w*w3.w;
                }
            }
#pragma unroll
            for (int rr = 0; rr < BB; rr++) {
                float4 gv = make_float4(acc[rr][0]+bias4.x, acc[rr][1]+bias4.y,
                                        acc[rr][2]+bias4.z, acc[rr][3]+bias4.w);
                *(float4*)&gh_s[rr][tid*4] = gv;
            }
        }
        __syncthreads();
#pragma unroll
        for (int rr = 0; rr < BB; rr++) {
            int gr = gx_per_bt ? rr : 0;
            float xr = gx_s[gr][tid], xz = gx_s[gr][H_+tid], xn = gx_s[gr][2*H_+tid];
            float hr = gh_s[rr][tid], hz = gh_s[rr][H_+tid], hn = gh_s[rr][2*H_+tid];
            float rg = 1.f / (1.f + __expf(-(xr + hr)));
            float ug = 1.f / (1.f + __expf(-(xz + hz)));
            float ng = tanhf(xn + rg * hn);
            float hold = h_s[rr][tid];
            float hnew = (1.f - ug) * ng + ug * hold;
            h_s[rr][tid] = hnew;
            size_t row = (size_t)(b0 + rr) * T_ + step;
            if (out_mode == 0) store_act_split(g_A2y0, row, tid, hnew);
            else               y[row * H_ + tid] = hnew;
        }
        __syncthreads();
    }
}

// ---------------- LayerNorm + ELU -> split bf16 ----------------
__global__ void k_ln_elu(const float* __restrict__ y, const float* __restrict__ lng,
                         const float* __restrict__ lnb) {
    int warp = threadIdx.x >> 5, lane = threadIdx.x & 31;
    int row = blockIdx.x * 8 + warp;
    const float* p = y + (size_t)row * H_;
    float v[8], s = 0.f, sq = 0.f;
#pragma unroll
    for (int i = 0; i < 8; i++) { v[i] = p[lane + 32*i]; s += v[i]; sq += v[i]*v[i]; }
#pragma unroll
    for (int o = 16; o; o >>= 1) {
        s  += __shfl_xor_sync(0xffffffffu, s,  o);
        sq += __shfl_xor_sync(0xffffffffu, sq, o);
    }
    float mu  = s  * (1.f / H_);
    float var = sq * (1.f / H_) - mu * mu;
    float inv = rsqrtf(var + 1e-5f);
#pragma unroll
    for (int i = 0; i < 8; i++) {
        int c = lane + 32*i;
        float t = elu1((v[i] - mu) * inv * lng[c] + lnb[c]);
        store_act_split(g_A2out, (size_t)row, c, t);
    }
}

// ---------------- launch ----------------
extern "C" void kernel_launch(void* const* d_in, const int* in_sizes, int n_in,
                              void* d_out, int out_size) {
    const float* z      = (const float*)d_in[0];
    const float* W_init = (const float*)d_in[1];
    const float* b_init = (const float*)d_in[2];
    const float* emb    = (const float*)d_in[3];
    const float* W_ih0  = (const float*)d_in[4];
    const float* W_hh0  = (const float*)d_in[5];
    const float* b_ih0  = (const float*)d_in[6];
    const float* b_hh0  = (const float*)d_in[7];
    const float* W_ih1  = (const float*)d_in[8];
    const float* W_hh1  = (const float*)d_in[9];
    const float* b_ih1  = (const float*)d_in[10];
    const float* b_hh1  = (const float*)d_in[11];
    const float* ln_g   = (const float*)d_in[12];
    const float* ln_b   = (const float*)d_in[13];
    const float* W_out  = (const float*)d_in[14];
    const float* b_out  = (const float*)d_in[15];

    float *p_WT0, *p_WT1, *p_y0, *p_gx0, *p_gx1;
    __nv_bfloat16 *p_A2y0, *p_A2out, *p_Wb2, *p_Wih1b2;
    cudaGetSymbolAddress((void**)&p_WT0, g_WT0);
    cudaGetSymbolAddress((void**)&p_WT1, g_WT1);
    cudaGetSymbolAddress((void**)&p_y0,  g_y0);
    cudaGetSymbolAddress((void**)&p_gx0, g_gx0);
    cudaGetSymbolAddress((void**)&p_gx1, g_gx1);
    cudaGetSymbolAddress((void**)&p_A2y0, g_A2y0);
    cudaGetSymbolAddress((void**)&p_A2out, g_A2out);
    cudaGetSymbolAddress((void**)&p_Wb2, g_Wb2);
    cudaGetSymbolAddress((void**)&p_Wih1b2, g_Wih1b2);

    cudaFuncSetAttribute(gemm_mma, cudaFuncAttributeMaxDynamicSharedMemorySize, 65536);

    // weight prep (independent)
    k_transpose<<<H_*G3_/256, 256>>>(W_hh0, p_WT0);
    k_transpose<<<H_*G3_/256, 256>>>(W_hh1, p_WT1);
    k_wsplit<<<G3_, 256>>>(W_ih1, p_Wih1b2, G3_);
    k_wsplit<<<PPAD, 256>>>(W_out, p_Wb2, P_);
    k_h0<<<B_*H_/256, 256>>>(z, W_init, b_init);
    k_gx0<<<G3_/256, 256>>>(emb, W_ih0, b_ih0);

    // layer 0 scan -> split bf16 A
    gru_scan<<<B_/BB, 256>>>(p_WT0, b_hh0, p_gx0, 0, nullptr, 0);

    // gx1 = y0 @ W_ih1^T + b_ih1  (tensor cores)
    gemm_mma<<<dim3(G3_/128, BT_/128), 256, 65536>>>(p_A2y0, p_Wih1b2, b_ih1, p_gx1, G3_, G3_);

    // layer 1 scan -> fp32 y
    gru_scan<<<B_/BB, 256>>>(p_WT1, b_hh1, p_gx1, 1, p_y0, 1);

    // LayerNorm + ELU -> split bf16 A
    k_ln_elu<<<BT_/8, 256>>>(p_y0, ln_g, ln_b);

    // logits = yln @ W_out^T + b_out
    gemm_mma<<<dim3(PPAD/128, BT_/128), 256, 65536>>>(p_A2out, p_Wb2, b_out, (float*)d_out, P_, P_);
}

// round 5
// speedup vs baseline: 1.6845x; 1.0012x over previous
#include <cuda_runtime.h>
#include <cuda_bf16.h>
#include <cstdint>
#include <math.h>

#define B_  512
#define Z_  64
#define H_  256
#define T_  64
#define P_  10000
#define G3_ 768
#define BT_ (B_*T_)
#define PPAD 10112   // 79*128
#define KS_ 768      // split-K: [Ah, Ah, Al] x [Wh, Wl, Wh]

// ---------------- scratch (no allocations allowed) ----------------
__device__ float g_h0[B_*H_];
__device__ float g_gx0[G3_];
__device__ float g_WT0[H_*G3_];
__device__ float g_WT1[H_*G3_];
__device__ float g_y0[BT_*H_];
__device__ float g_gx1[(size_t)BT_*G3_];
__device__ __align__(256) __nv_bfloat16 g_A2y0[(size_t)BT_*KS_];
__device__ __align__(256) __nv_bfloat16 g_A2out[(size_t)BT_*KS_];
__device__ __align__(256) __nv_bfloat16 g_Wb2[(size_t)PPAD*KS_];
__device__ __align__(256) __nv_bfloat16 g_Wih1b2[(size_t)G3_*KS_];

__device__ __forceinline__ float elu1(float x) {
    return x > 0.f ? x : (__expf(x) - 1.f);
}

__device__ __forceinline__ uint32_t smem_u32(const void* p) {
    uint32_t a;
    asm("{ .reg .u64 t; cvta.to.shared.u64 t, %1; cvt.u32.u64 %0, t; }" : "=r"(a) : "l"(p));
    return a;
}
__device__ __forceinline__ void cp16(uint32_t s, const void* g) {
    asm volatile("cp.async.cg.shared.global [%0], [%1], 16;" :: "r"(s), "l"(g));
}
__device__ __forceinline__ void ldsm4(uint32_t& a0, uint32_t& a1, uint32_t& a2, uint32_t& a3,
                                      uint32_t addr) {
    asm volatile("ldmatrix.sync.aligned.m8n8.x4.shared.b16 {%0,%1,%2,%3}, [%4];"
        : "=r"(a0), "=r"(a1), "=r"(a2), "=r"(a3) : "r"(addr));
}
__device__ __forceinline__ void mma16816(float* d, uint32_t a0, uint32_t a1, uint32_t a2,
                                         uint32_t a3, uint32_t b0, uint32_t b1) {
    asm volatile("mma.sync.aligned.m16n8k16.row.col.f32.bf16.bf16.f32 "
        "{%0,%1,%2,%3}, {%4,%5,%6,%7}, {%8,%9}, {%0,%1,%2,%3};"
        : "+f"(d[0]), "+f"(d[1]), "+f"(d[2]), "+f"(d[3])
        : "r"(a0), "r"(a1), "r"(a2), "r"(a3), "r"(b0), "r"(b1));
}

// ================= bf16 split-K tensor GEMM: C[M,ldc] = A2[M,768] @ B2[N,768]^T + bias
// 128x128 tile, 8 warps (4 m x 2 n), warp tile 32x64, K chunks of 64.
// 3-stage cp.async pipeline, ONE __syncthreads per chunk.
#define ST_B 32768          // bytes per stage (A 16KB + B 16KB)
#define GSM  (3 * ST_B)     // 96 KB
__global__ __launch_bounds__(256, 2) void gemm_mma(
        const __nv_bfloat16* __restrict__ A2, const __nv_bfloat16* __restrict__ B2,
        const float* __restrict__ bias, float* __restrict__ C, int N, int ldc) {
    extern __shared__ char sm[];
    const uint32_t sbase = smem_u32(sm);
    const int tid = threadIdx.x, lane = tid & 31, wid = tid >> 5;
    const int m0t = blockIdx.y << 7, n0t = blockIdx.x << 7;

    // ---- cp.async mapping: thread covers 4 consecutive 16B units of one row (128B/row chunk)
    const int lrow = tid >> 1;
    const int lkb  = (tid & 1) * 4;
    uint32_t lsoff[4];
#pragma unroll
    for (int j = 0; j < 4; ++j)
        lsoff[j] = lrow * 128 + ((((lkb + j) << 4)) ^ ((lrow & 7) << 4));
    const char* gAr = (const char*)A2 + (size_t)(m0t + lrow) * (KS_ * 2) + lkb * 16;
    const char* gBr = (const char*)B2 + (size_t)(n0t + lrow) * (KS_ * 2) + lkb * 16;

    // ---- ldmatrix per-thread addressing
    const int g = lane >> 3, r = lane & 7;
    const uint32_t rx = r << 4;
    const uint32_t aKbx = (g >> 1) << 4;
    const uint32_t bKbx = (g & 1) << 4;
    uint32_t aRowOff[2], bRowOff[4];
#pragma unroll
    for (int fm = 0; fm < 2; ++fm)
        aRowOff[fm] = (uint32_t)(((wid & 3) * 32 + ((g & 1) << 3) + r + fm * 16) * 128);
#pragma unroll
    for (int p = 0; p < 4; ++p)
        bRowOff[p] = (uint32_t)(((wid >> 2) * 64 + ((g >> 1) << 3) + r + p * 16) * 128);

    float acc[2][8][4];
#pragma unroll
    for (int i = 0; i < 2; ++i)
#pragma unroll
        for (int j = 0; j < 8; ++j)
#pragma unroll
            for (int k = 0; k < 4; ++k) acc[i][j][k] = 0.f;

    // prologue: chunks 0,1 -> stages 0,1
#pragma unroll
    for (int c = 0; c < 2; ++c) {
        const uint32_t sa = sbase + c * ST_B;
        const char* pa = gAr + c * 128;
        const char* pb = gBr + c * 128;
#pragma unroll
        for (int j = 0; j < 4; ++j) {
            cp16(sa + lsoff[j], pa + j * 16);
            cp16(sa + 16384 + lsoff[j], pb + j * 16);
        }
        asm volatile("cp.async.commit_group;");
    }

    int stage = 0;
    int nstage = 2;
    for (int c = 0; c < 12; ++c) {
        if (c < 11) asm volatile("cp.async.wait_group 1;");
        else        asm volatile("cp.async.wait_group 0;");
        __syncthreads();

        if (c + 2 < 12) {
            const uint32_t sa = sbase + nstage * ST_B;
            const char* pa = gAr + (c + 2) * 128;
            const char* pb = gBr + (c + 2) * 128;
#pragma unroll
            for (int j = 0; j < 4; ++j) {
                cp16(sa + lsoff[j], pa + j * 16);
                cp16(sa + 16384 + lsoff[j], pb + j * 16);
            }
            asm volatile("cp.async.commit_group;");
        }

        const uint32_t aB = sbase + stage * ST_B;
        const uint32_t bB = aB + 16384;
#pragma unroll
        for (int kk = 0; kk < 4; ++kk) {
            const uint32_t akoff = ((uint32_t)(kk * 32) + aKbx) ^ rx;
            const uint32_t bkoff = ((uint32_t)(kk * 32) + bKbx) ^ rx;
            uint32_t a[2][4], bb[4][4];
#pragma unroll
            for (int fm = 0; fm < 2; ++fm)
                ldsm4(a[fm][0], a[fm][1], a[fm][2], a[fm][3], aB + aRowOff[fm] + akoff);
#pragma unroll
            for (int p = 0; p < 4; ++p)
                ldsm4(bb[p][0], bb[p][1], bb[p][2], bb[p][3], bB + bRowOff[p] + bkoff);
#pragma unroll
            for (int fm = 0; fm < 2; ++fm)
#pragma unroll
                for (int p = 0; p < 4; ++p) {
                    mma16816(acc[fm][2 * p],     a[fm][0], a[fm][1], a[fm][2], a[fm][3],
                             bb[p][0], bb[p][1]);
                    mma16816(acc[fm][2 * p + 1], a[fm][0], a[fm][1], a[fm][2], a[fm][3],
                             bb[p][2], bb[p][3]);
                }
        }
        stage  = (stage  == 2) ? 0 : stage  + 1;
        nstage = (nstage == 2) ? 0 : nstage + 1;
    }

    // epilogue
#pragma unroll
    for (int fm = 0; fm < 2; ++fm) {
        const int mrow = m0t + (wid & 3) * 32 + fm * 16 + (lane >> 2);
        float* c0 = C + (size_t)mrow * ldc;
        float* c1 = C + (size_t)(mrow + 8) * ldc;
#pragma unroll
        for (int bn = 0; bn < 8; ++bn) {
            const int n = n0t + (wid >> 2) * 64 + bn * 8 + (lane & 3) * 2;
            if (n < N) {
                const float bv = bias[n];
                c0[n] = acc[fm][bn][0] + bv;
                c1[n] = acc[fm][bn][2] + bv;
            }
            if (n + 1 < N) {
                const float bv = bias[n + 1];
                c0[n + 1] = acc[fm][bn][1] + bv;
                c1[n + 1] = acc[fm][bn][3] + bv;
            }
        }
    }
}

// ---------------- prep kernels ----------------
__global__ void k_transpose(const float* __restrict__ W, float* __restrict__ WT) {
    int idx = blockIdx.x * 256 + threadIdx.x;
    int k = idx / G3_, g = idx - k * G3_;
    WT[idx] = W[g * H_ + k];
}

__global__ void k_h0(const float* __restrict__ z, const float* __restrict__ Wi,
                     const float* __restrict__ bi) {
    int idx = blockIdx.x * 256 + threadIdx.x;
    int b = idx >> 8, h = idx & 255;
    float s = bi[h];
    const float* zr = z + b * Z_;
    const float* wr = Wi + h * Z_;
#pragma unroll 16
    for (int i = 0; i < Z_; i++) s += zr[i] * wr[i];
    g_h0[idx] = elu1(s);
}

__global__ void k_gx0(const float* __restrict__ emb, const float* __restrict__ Wih,
                      const float* __restrict__ bih) {
    int gg = blockIdx.x * 256 + threadIdx.x;
    float s = bih[gg];
    const float* wr = Wih + gg * H_;
#pragma unroll 8
    for (int i = 0; i < H_; i++) s += emb[i] * wr[i];
    g_gx0[gg] = s;
}

// weights: [Wh, Wl, Wh]
__global__ void k_wsplit(const float* __restrict__ W, __nv_bfloat16* __restrict__ O, int N) {
    int idx = blockIdx.x * 256 + threadIdx.x;
    int row = idx >> 8, col = idx & 255;
    float x = (row < N) ? W[row * 256 + col] : 0.f;
    __nv_bfloat16 hi = __float2bfloat16(x);
    float lo = x - __bfloat162float(hi);
    size_t base = (size_t)row * KS_;
    O[base + col]       = hi;
    O[base + 256 + col] = __float2bfloat16(lo);
    O[base + 512 + col] = hi;
}

// activations: [Ah, Ah, Al]
__device__ __forceinline__ void store_act_split(__nv_bfloat16* dst, size_t row, int col, float v) {
    __nv_bfloat16 hi = __float2bfloat16(v);
    float lo = v - __bfloat162float(hi);
    size_t base = row * KS_;
    dst[base + col]       = hi;
    dst[base + 256 + col] = hi;
    dst[base + 512 + col] = __float2bfloat16(lo);
}

// ---------------- GRU scan ----------------
#define BB 4
__global__ __launch_bounds__(256) void gru_scan(
        const float* __restrict__ WT, const float* __restrict__ bhh,
        const float* __restrict__ gx, int gx_per_bt,
        float* __restrict__ y, int out_mode) {   // 0: split bf16 -> g_A2y0 ; 1: fp32 -> y
    __shared__ __align__(16) float h_s [BB][H_];
    __shared__ __align__(16) float gh_s[BB][G3_];
    __shared__ __align__(16) float gx_s[BB][G3_];
    int tid = threadIdx.x;
    int b0 = blockIdx.x * BB;

#pragma unroll
    for (int rr = 0; rr < BB; rr++) h_s[rr][tid] = g_h0[(b0 + rr) * H_ + tid];
    if (!gx_per_bt) {
        for (int i = tid; i < G3_; i += 256) gx_s[0][i] = gx[i];
    }
    float4 bias4 = make_float4(0.f, 0.f, 0.f, 0.f);
    if (tid < 192) bias4 = *(const float4*)(bhh + tid * 4);
    __syncthreads();

    for (int step = 0; step < T_; step++) {
        if (gx_per_bt) {
#pragma unroll
            for (int i = 0; i < 3; i++) {
                int j = tid + i * 256;
                int rr = j / 192;
                int cc = (j - rr * 192) * 4;
                *(float4*)&gx_s[rr][cc] =
                    *(const float4*)&gx[((size_t)(b0 + rr) * T_ + step) * G3_ + cc];
            }
        }
        float acc[BB][4];
#pragma unroll
        for (int rr = 0; rr < BB; rr++) { acc[rr][0]=0.f; acc[rr][1]=0.f; acc[rr][2]=0.f; acc[rr][3]=0.f; }
        if (tid < 192) {
            const float* wp = WT + tid * 4;
#pragma unroll 4
            for (int k = 0; k < H_; k += 4) {
                float4 w0 = *(const float4*)(wp + (size_t)(k+0) * G3_);
                float4 w1 = *(const float4*)(wp + (size_t)(k+1) * G3_);
                float4 w2 = *(const float4*)(wp + (size_t)(k+2) * G3_);
                float4 w3 = *(const float4*)(wp + (size_t)(k+3) * G3_);
#pragma unroll
                for (int rr = 0; rr < BB; rr++) {
                    float4 hv = *(const float4*)&h_s[rr][k];
                    acc[rr][0] += hv.x*w0.x + hv.y*w1.x + hv.z*w2.x + hv.w*w3.x;
                    acc[rr][1] += hv.x*w0.y + hv.y*w1.y + hv.z*w2.y + hv.w*w3.y;
                    acc[rr][2] += hv.x*w0.z + hv.y*w1.z + hv.z*w2.z + hv.w*w3.z;
                    acc[rr][3] += hv.x*w0.w + hv.y*w1.w + hv.z*w2.w + hv.w*w3.w;
                }
            }
#pragma unroll
            for (int rr = 0; rr < BB; rr++) {
                float4 gv = make_float4(acc[rr][0]+bias4.x, acc[rr][1]+bias4.y,
                                        acc[rr][2]+bias4.z, acc[rr][3]+bias4.w);
                *(float4*)&gh_s[rr][tid*4] = gv;
            }
        }
        __syncthreads();
#pragma unroll
        for (int rr = 0; rr < BB; rr++) {
            int gr = gx_per_bt ? rr : 0;
            float xr = gx_s[gr][tid], xz = gx_s[gr][H_+tid], xn = gx_s[gr][2*H_+tid];
            float hr = gh_s[rr][tid], hz = gh_s[rr][H_+tid], hn = gh_s[rr][2*H_+tid];
            float rg = 1.f / (1.f + __expf(-(xr + hr)));
            float ug = 1.f / (1.f + __expf(-(xz + hz)));
            float ng = tanhf(xn + rg * hn);
            float hold = h_s[rr][tid];
            float hnew = (1.f - ug) * ng + ug * hold;
            h_s[rr][tid] = hnew;
            size_t row = (size_t)(b0 + rr) * T_ + step;
            if (out_mode == 0) store_act_split(g_A2y0, row, tid, hnew);
            else               y[row * H_ + tid] = hnew;
        }
        __syncthreads();
    }
}

// ---------------- LayerNorm + ELU -> split bf16 ----------------
__global__ void k_ln_elu(const float* __restrict__ y, const float* __restrict__ lng,
                         const float* __restrict__ lnb) {
    int warp = threadIdx.x >> 5, lane = threadIdx.x & 31;
    int row = blockIdx.x * 8 + warp;
    const float* p = y + (size_t)row * H_;
    float v[8], s = 0.f, sq = 0.f;
#pragma unroll
    for (int i = 0; i < 8; i++) { v[i] = p[lane + 32*i]; s += v[i]; sq += v[i]*v[i]; }
#pragma unroll
    for (int o = 16; o; o >>= 1) {
        s  += __shfl_xor_sync(0xffffffffu, s,  o);
        sq += __shfl_xor_sync(0xffffffffu, sq, o);
    }
    float mu  = s  * (1.f / H_);
    float var = sq * (1.f / H_) - mu * mu;
    float inv = rsqrtf(var + 1e-5f);
#pragma unroll
    for (int i = 0; i < 8; i++) {
        int c = lane + 32*i;
        float t = elu1((v[i] - mu) * inv * lng[c] + lnb[c]);
        store_act_split(g_A2out, (size_t)row, c, t);
    }
}

// ---------------- launch ----------------
extern "C" void kernel_launch(void* const* d_in, const int* in_sizes, int n_in,
                              void* d_out, int out_size) {
    const float* z      = (const float*)d_in[0];
    const float* W_init = (const float*)d_in[1];
    const float* b_init = (const float*)d_in[2];
    const float* emb    = (const float*)d_in[3];
    const float* W_ih0  = (const float*)d_in[4];
    const float* W_hh0  = (const float*)d_in[5];
    const float* b_ih0  = (const float*)d_in[6];
    const float* b_hh0  = (const float*)d_in[7];
    const float* W_ih1  = (const float*)d_in[8];
    const float* W_hh1  = (const float*)d_in[9];
    const float* b_ih1  = (const float*)d_in[10];
    const float* b_hh1  = (const float*)d_in[11];
    const float* ln_g   = (const float*)d_in[12];
    const float* ln_b   = (const float*)d_in[13];
    const float* W_out  = (const float*)d_in[14];
    const float* b_out  = (const float*)d_in[15];

    float *p_WT0, *p_WT1, *p_y0, *p_gx0, *p_gx1;
    __nv_bfloat16 *p_A2y0, *p_A2out, *p_Wb2, *p_Wih1b2;
    cudaGetSymbolAddress((void**)&p_WT0, g_WT0);
    cudaGetSymbolAddress((void**)&p_WT1, g_WT1);
    cudaGetSymbolAddress((void**)&p_y0,  g_y0);
    cudaGetSymbolAddress((void**)&p_gx0, g_gx0);
    cudaGetSymbolAddress((void**)&p_gx1, g_gx1);
    cudaGetSymbolAddress((void**)&p_A2y0, g_A2y0);
    cudaGetSymbolAddress((void**)&p_A2out, g_A2out);
    cudaGetSymbolAddress((void**)&p_Wb2, g_Wb2);
    cudaGetSymbolAddress((void**)&p_Wih1b2, g_Wih1b2);

    cudaFuncSetAttribute(gemm_mma, cudaFuncAttributeMaxDynamicSharedMemorySize, GSM);

    // weight prep (independent)
    k_transpose<<<H_*G3_/256, 256>>>(W_hh0, p_WT0);
    k_transpose<<<H_*G3_/256, 256>>>(W_hh1, p_WT1);
    k_wsplit<<<G3_, 256>>>(W_ih1, p_Wih1b2, G3_);
    k_wsplit<<<PPAD, 256>>>(W_out, p_Wb2, P_);
    k_h0<<<B_*H_/256, 256>>>(z, W_init, b_init);
    k_gx0<<<G3_/256, 256>>>(emb, W_ih0, b_ih0);

    // layer 0 scan -> split bf16 A
    gru_scan<<<B_/BB, 256>>>(p_WT0, b_hh0, p_gx0, 0, nullptr, 0);

    // gx1 = y0 @ W_ih1^T + b_ih1  (tensor cores)
    gemm_mma<<<dim3(G3_/128, BT_/128), 256, GSM>>>(p_A2y0, p_Wih1b2, b_ih1, p_gx1, G3_, G3_);

    // layer 1 scan -> fp32 y
    gru_scan<<<B_/BB, 256>>>(p_WT1, b_hh1, p_gx1, 1, p_y0, 1);

    // LayerNorm + ELU -> split bf16 A
    k_ln_elu<<<BT_/8, 256>>>(p_y0, ln_g, ln_b);

    // logits = yln @ W_out^T + b_out
    gemm_mma<<<dim3(PPAD/128, BT_/128), 256, GSM>>>(p_A2out, p_Wb2, b_out, (float*)d_out, P_, P_);
}